// round 1
// baseline (speedup 1.0000x reference)
#include <cuda_runtime.h>
#include <cuda_bf16.h>

// ---------------------------------------------------------------------------
// MatchingNetwork: sup/tgt = rows @ Wt + b ; sims ; softmax-attend ; acc+CE.
// Round 1: fp32 GEMM with packed fma.rn.f32x2 (FFMA2), K-split for occupancy.
// ---------------------------------------------------------------------------

#define B_SZ   256
#define S_SZ   20
#define V_SZ   20000
#define C_SZ   20
#define D_SZ   64
#define M_SUP  (B_SZ * S_SZ)      // 5120
#define M_ALL  (M_SUP + B_SZ)     // 5376 (target rows appended)
#define KSPLIT 10
#define KSLICE (V_SZ / KSPLIT)    // 2000
#define KB     40                 // k-tile
#define TILEM  64

typedef unsigned long long ull;

// ---- device scratch (static globals: allocation-free at run time) ----------
__device__ float g_Wt[(size_t)V_SZ * D_SZ];                    // 5.12 MB
__device__ float g_part[(size_t)KSPLIT * M_ALL * D_SZ];        // 13.76 MB
__device__ float g_sup[(size_t)M_ALL * D_SZ];                  // 1.38 MB
__device__ float g_pb[2 * B_SZ];                               // correct, loss

// ---- packed f32x2 helpers ---------------------------------------------------
__device__ __forceinline__ ull fma2(ull a, ull b, ull c) {
    ull d;
    asm("fma.rn.f32x2 %0, %1, %2, %3;" : "=l"(d) : "l"(a), "l"(b), "l"(c));
    return d;
}
__device__ __forceinline__ ull pack2(float x, float y) {
    ull r;
    asm("mov.b64 %0, {%1, %2};" : "=l"(r) : "f"(x), "f"(y));
    return r;
}
__device__ __forceinline__ float2 unpack2(ull v) {
    float2 r;
    asm("mov.b64 {%0, %1}, %2;" : "=f"(r.x), "=f"(r.y) : "l"(v));
    return r;
}

// ---- K0: transpose W [64, 20000] -> Wt [20000, 64] -------------------------
__global__ void transpose_kernel(const float* __restrict__ W) {
    int idx = blockIdx.x * 256 + threadIdx.x;        // grid covers V*D exactly
    int v = idx >> 6;
    int d = idx & 63;
    g_Wt[idx] = W[(size_t)d * V_SZ + v];
}

// ---- K1: big GEMM (rows = support images ++ target images) -----------------
// grid = (M_ALL/TILEM = 84, KSPLIT = 10), block = 128 threads.
// CTA tile 64x64; thread tile 4 rows x 8 cols (4 f32x2 pairs).
__global__ __launch_bounds__(128) void gemm_kernel(
    const float* __restrict__ img, const float* __restrict__ tgtim)
{
    __shared__ float As[TILEM][KB + 1];   // +1 pad: conflict-free column reads
    __shared__ float Bs[KB * D_SZ];

    const int row0 = blockIdx.x * TILEM;
    const int ks   = blockIdx.y;
    const int tid  = threadIdx.x;
    const int tm   = tid >> 3;   // 0..15
    const int tn   = tid & 7;    // 0..7

    ull acc[4][4];
    #pragma unroll
    for (int i = 0; i < 4; ++i)
        #pragma unroll
        for (int j = 0; j < 4; ++j) acc[i][j] = 0ull;

    const int kslice0 = ks * KSLICE;

    for (int kt = 0; kt < KSLICE / KB; ++kt) {
        const int kbase = kslice0 + kt * KB;

        // load A tile: 64 rows x 40 cols = 640 float4, 5 per thread
        #pragma unroll
        for (int j = 0; j < 5; ++j) {
            int idx = tid + 128 * j;
            int row = idx / 10;
            int kq  = idx % 10;
            int rowg = row0 + row;
            const float* p = (rowg < M_SUP)
                ? (img   + (size_t)rowg * V_SZ)
                : (tgtim + (size_t)(rowg - M_SUP) * V_SZ);
            float4 v = *reinterpret_cast<const float4*>(p + kbase + kq * 4);
            As[row][kq * 4 + 0] = v.x;
            As[row][kq * 4 + 1] = v.y;
            As[row][kq * 4 + 2] = v.z;
            As[row][kq * 4 + 3] = v.w;
        }
        // load B tile: 40 k-rows x 64 d = 640 float4, 5 per thread
        #pragma unroll
        for (int j = 0; j < 5; ++j) {
            int idx = tid + 128 * j;
            int kr = idx >> 4;
            int dq = idx & 15;
            float4 v = *reinterpret_cast<const float4*>(
                &g_Wt[(size_t)(kbase + kr) * D_SZ + dq * 4]);
            *reinterpret_cast<float4*>(&Bs[kr * D_SZ + dq * 4]) = v;
        }
        __syncthreads();

        #pragma unroll
        for (int k = 0; k < KB; ++k) {
            ull aa[4];
            #pragma unroll
            for (int i = 0; i < 4; ++i) {
                float a = As[tm * 4 + i][k];
                aa[i] = pack2(a, a);
            }
            ull bb[4];
            #pragma unroll
            for (int j = 0; j < 4; ++j)
                bb[j] = *reinterpret_cast<const ull*>(&Bs[k * D_SZ + tn * 8 + j * 2]);
            #pragma unroll
            for (int i = 0; i < 4; ++i)
                #pragma unroll
                for (int j = 0; j < 4; ++j)
                    acc[i][j] = fma2(aa[i], bb[j], acc[i][j]);
        }
        __syncthreads();
    }

    // store partials
    #pragma unroll
    for (int i = 0; i < 4; ++i) {
        int rowg = row0 + tm * 4 + i;
        float* dst = &g_part[((size_t)ks * M_ALL + rowg) * D_SZ + tn * 8];
        #pragma unroll
        for (int j = 0; j < 4; ++j) {
            float2 f = unpack2(acc[i][j]);
            *reinterpret_cast<float2*>(dst + j * 2) = f;
        }
    }
}

// ---- K2: reduce K-split partials + bias -> g_sup ----------------------------
__global__ void reduce_kernel(const float* __restrict__ bias) {
    int idx = blockIdx.x * 256 + threadIdx.x;        // grid covers M_ALL*D exactly
    int d = idx & 63;
    float s = bias[d];
    #pragma unroll
    for (int ks = 0; ks < KSPLIT; ++ks)
        s += g_part[(size_t)ks * M_ALL * D_SZ + idx];
    g_sup[idx] = s;
}

// ---- K3: per-episode similarities / softmax / preds / argmax / CE ----------
__global__ void sim_kernel(const float* __restrict__ onehot,
                           const int* __restrict__ tgty)
{
    int b = blockIdx.x;
    int lane = threadIdx.x;
    __shared__ float sims[S_SZ];

    const float* tgt = &g_sup[(size_t)(M_SUP + b) * D_SZ];
    if (lane < S_SZ) {
        const float* sp = &g_sup[(size_t)(b * S_SZ + lane) * D_SZ];
        float dot = 0.f, mag = 0.f;
        #pragma unroll
        for (int d = 0; d < D_SZ; ++d) {
            float s = sp[d];
            dot += s * tgt[d];
            mag += s * s;
        }
        sims[lane] = dot * rsqrtf(fmaxf(mag, 1e-10f));
    }
    __syncwarp();

    if (lane == 0) {
        float m = sims[0];
        for (int s = 1; s < S_SZ; ++s) m = fmaxf(m, sims[s]);
        float e[S_SZ], sum = 0.f;
        for (int s = 0; s < S_SZ; ++s) { e[s] = expf(sims[s] - m); sum += e[s]; }
        float inv = 1.f / sum;

        float preds[C_SZ];
        for (int c = 0; c < C_SZ; ++c) preds[c] = 0.f;
        for (int s = 0; s < S_SZ; ++s) {
            float a = e[s] * inv;
            const float* oh = &onehot[((size_t)b * S_SZ + s) * C_SZ];
            for (int c = 0; c < C_SZ; ++c) preds[c] += a * oh[c];
        }

        int best = 0; float bv = preds[0];
        for (int c = 1; c < C_SZ; ++c)
            if (preds[c] > bv) { bv = preds[c]; best = c; }

        int y = tgty[b];
        float pm = preds[0];
        for (int c = 1; c < C_SZ; ++c) pm = fmaxf(pm, preds[c]);
        float lse = 0.f;
        for (int c = 0; c < C_SZ; ++c) lse += expf(preds[c] - pm);
        lse = logf(lse);
        float loss = -(preds[y] - pm - lse);

        g_pb[b]          = (best == y) ? 1.f : 0.f;
        g_pb[B_SZ + b]   = loss;
    }
}

// ---- K4: deterministic final reduction -> d_out ----------------------------
__global__ void finalize_kernel(float* __restrict__ out) {
    __shared__ float sc[B_SZ], sl[B_SZ];
    int t = threadIdx.x;
    sc[t] = g_pb[t];
    sl[t] = g_pb[B_SZ + t];
    __syncthreads();
    for (int off = 128; off > 0; off >>= 1) {
        if (t < off) { sc[t] += sc[t + off]; sl[t] += sl[t + off]; }
        __syncthreads();
    }
    if (t == 0) {
        out[0] = sc[0] * (1.f / (float)B_SZ);   // accuracy
        out[1] = sl[0] * (1.f / (float)B_SZ);   // crossentropy_loss
    }
}

// ---------------------------------------------------------------------------
extern "C" void kernel_launch(void* const* d_in, const int* in_sizes, int n_in,
                              void* d_out, int out_size)
{
    const float* img    = (const float*)d_in[0];   // [256,20,20000]
    const float* onehot = (const float*)d_in[1];   // [256,20,20]
    const float* tgtim  = (const float*)d_in[2];   // [256,20000]
    const int*   tgty   = (const int*)  d_in[3];   // [256]
    const float* W      = (const float*)d_in[4];   // [64,20000]
    const float* bias   = (const float*)d_in[5];   // [64]
    float* out = (float*)d_out;                    // [2]

    transpose_kernel<<<(V_SZ * D_SZ) / 256, 256>>>(W);
    gemm_kernel<<<dim3(M_ALL / TILEM, KSPLIT), 128>>>(img, tgtim);
    reduce_kernel<<<(M_ALL * D_SZ) / 256, 256>>>(bias);
    sim_kernel<<<B_SZ, 32>>>(onehot, tgty);
    finalize_kernel<<<1, B_SZ>>>(out);
}

// round 3
// speedup vs baseline: 2.3994x; 2.3994x over previous
#include <cuda_runtime.h>
#include <cuda_bf16.h>
#include <cstdint>

// ---------------------------------------------------------------------------
// MatchingNetwork — Round 3: split-bf16 GEMM on mma.sync (HMMA) —
// compute_103-safe PTX only (no tcgen05). 3-term: Ah*Bh + Ah*Bl + Al*Bh.
// ---------------------------------------------------------------------------

#define B_SZ   256
#define S_SZ   20
#define V_SZ   20000
#define C_SZ   20
#define D_SZ   64
#define M_SUP  (B_SZ * S_SZ)      // 5120
#define M_ALL  (M_SUP + B_SZ)     // 5376
#define KSPLIT 7
#define PITCH  176u               // smem row pitch bytes (80 bf16 = 160B, padded)

// smem offsets (single buffer)
#define OF_AHI 0u
#define OF_ALO 22528u             // 128*176
#define OF_BHI 45056u
#define OF_BLO 56320u             // +64*176
#define SMEM_TOTAL 67584

// ---- device scratch ---------------------------------------------------------
__device__ float         g_part[(size_t)KSPLIT * M_ALL * D_SZ];
__device__ float         g_sup[(size_t)M_ALL * D_SZ];
__device__ __nv_bfloat16 g_Whi[(size_t)D_SZ * V_SZ];
__device__ __nv_bfloat16 g_Wlo[(size_t)D_SZ * V_SZ];
__device__ float         g_pb[2 * B_SZ];

// ---- PTX helpers ------------------------------------------------------------
__device__ __forceinline__ uint32_t smem_u32(const void* p) {
    uint32_t a;
    asm("{ .reg .u64 t; cvta.to.shared.u64 t, %1; cvt.u32.u64 %0, t; }"
        : "=r"(a) : "l"(p));
    return a;
}
__device__ __forceinline__ void sts32(uint32_t a, uint32_t v) {
    asm volatile("st.shared.b32 [%0], %1;" :: "r"(a), "r"(v));
}
__device__ __forceinline__ uint32_t cvt2bf(float lo, float hi) {
    uint32_t r;   // lower half <- lo, upper half <- hi
    asm("cvt.rn.bf16x2.f32 %0, %1, %2;" : "=r"(r) : "f"(hi), "f"(lo));
    return r;
}
__device__ __forceinline__ void cp16(uint32_t s, const void* g) {
    asm volatile("cp.async.cg.shared.global [%0], [%1], 16;" :: "r"(s), "l"(g));
}
#define CP_COMMIT() asm volatile("cp.async.commit_group;" ::: "memory")
#define CP_WAIT0()  asm volatile("cp.async.wait_group 0;" ::: "memory")

__device__ __forceinline__ void ldm4(uint32_t a, uint32_t r[4]) {
    asm volatile("ldmatrix.sync.aligned.m8n8.x4.shared.b16 {%0,%1,%2,%3}, [%4];"
        : "=r"(r[0]), "=r"(r[1]), "=r"(r[2]), "=r"(r[3]) : "r"(a));
}
__device__ __forceinline__ void mma16816(float c[4], const uint32_t a[4],
                                         const uint32_t* b) {
    asm volatile("mma.sync.aligned.m16n8k16.row.col.f32.bf16.bf16.f32 "
        "{%0,%1,%2,%3}, {%4,%5,%6,%7}, {%8,%9}, {%0,%1,%2,%3};"
        : "+f"(c[0]), "+f"(c[1]), "+f"(c[2]), "+f"(c[3])
        : "r"(a[0]), "r"(a[1]), "r"(a[2]), "r"(a[3]), "r"(b[0]), "r"(b[1]));
}

// ---- K0: split W into bf16 hi/lo ---------------------------------------------
__global__ void prep_w_kernel(const float* __restrict__ W) {
    int idx = blockIdx.x * 256 + threadIdx.x;          // covers D*V exactly
    float x  = W[idx];
    __nv_bfloat16 h = __float2bfloat16_rn(x);
    g_Whi[idx] = h;
    g_Wlo[idx] = __float2bfloat16_rn(x - __bfloat162float(h));
}

// ---- K1: split-bf16 HMMA GEMM --------------------------------------------------
// grid = (42 m-tiles, 7 k-slices), 128 threads (4 warps, warp tile m32 x n64)
__global__ __launch_bounds__(128) void gemm_kernel(
    const float* __restrict__ img, const float* __restrict__ tgtim)
{
    extern __shared__ char smem[];
    const uint32_t sb = smem_u32(smem);
    const int tid  = threadIdx.x;
    const int w    = tid >> 5;
    const int lane = tid & 31;
    const int row0 = blockIdx.x * 128;
    const int ks   = blockIdx.y;

    // k-slice in k16 steps: 1250 total -> 4x179 + 3x178
    const int sbeg = ks * 178 + (ks < 4 ? ks : 4);
    const int scnt = 178 + (ks < 4 ? 1 : 0);
    const int NCH  = (scnt + 4) / 5;                    // 36 chunks of <=5 steps

    const float* abase = (blockIdx.x < 40)
        ? img   + (size_t)row0 * V_SZ
        : tgtim + (size_t)(row0 - M_SUP) * V_SZ;

    // A fill mapping: 8 passes of 16 rows; 8 threads/row, 5 float2 each
    const int arow_l = tid >> 3;        // 0..15 (+16*pass)
    const int atc    = tid & 7;
    // B fill mapping: 2 threads/row, 5 x 16B each
    const int brow   = tid >> 1;        // 0..63
    const int bhalf  = tid & 1;

    // ldmatrix lane base addresses
    const uint32_t aLB = (uint32_t)(w * 32 + (lane & 15)) * PITCH
                       + (uint32_t)((lane >> 4) * 16);
    const uint32_t bLB = (uint32_t)((lane & 7) + ((lane >> 4) & 1) * 8) * PITCH
                       + (uint32_t)(((lane >> 3) & 1) * 16);

    float acc[2][8][4];
    #pragma unroll
    for (int mt = 0; mt < 2; ++mt)
        #pragma unroll
        for (int nt = 0; nt < 8; ++nt)
            #pragma unroll
            for (int i = 0; i < 4; ++i) acc[mt][nt][i] = 0.f;

    for (int c = 0; c < NCH; ++c) {
        const int nk = min(5, scnt - c * 5);            // k16 steps this chunk
        const int k0 = (sbeg + c * 5) * 16;             // element offset

        __syncthreads();                                 // smem free to refill

        // ---- B tiles via cp.async (bf16 hi/lo pre-split in gmem) ----
        {
            const char* gh = (const char*)(g_Whi + (size_t)brow * V_SZ + k0);
            const char* gl = (const char*)(g_Wlo + (size_t)brow * V_SZ + k0);
            uint32_t sB = sb + (uint32_t)brow * PITCH;
            #pragma unroll
            for (int j = 0; j < 5; ++j) {
                int piece = bhalf * 5 + j;
                if (piece < 2 * nk) {
                    cp16(sB + OF_BHI + piece * 16, gh + piece * 16);
                    cp16(sB + OF_BLO + piece * 16, gl + piece * 16);
                }
            }
            CP_COMMIT();
        }

        // ---- A tiles: LDG fp32 -> split bf16 hi/lo -> STS ----
        #pragma unroll
        for (int p = 0; p < 8; ++p) {
            const int rl = arow_l + p * 16;
            const float2* rp = (const float2*)(abase + (size_t)rl * V_SZ + k0);
            uint32_t sA = sb + (uint32_t)rl * PITCH;
            #pragma unroll
            for (int j = 0; j < 5; ++j) {
                if (j < nk) {
                    const int c2 = j * 8 + atc;          // float2 index
                    float2 v = rp[c2];
                    uint32_t h = cvt2bf(v.x, v.y);
                    float r0 = v.x - __uint_as_float(h << 16);
                    float r1 = v.y - __uint_as_float(h & 0xFFFF0000u);
                    uint32_t l = cvt2bf(r0, r1);
                    sts32(sA + OF_AHI + c2 * 4, h);
                    sts32(sA + OF_ALO + c2 * 4, l);
                }
            }
        }

        CP_WAIT0();
        __syncthreads();

        // ---- MMA over nk k16-steps ----
        for (int s = 0; s < nk; ++s) {
            const uint32_t sbyte = (uint32_t)s * 32;
            uint32_t ah[2][4], al[2][4];
            #pragma unroll
            for (int mt = 0; mt < 2; ++mt) {
                uint32_t a = sb + aLB + (uint32_t)mt * (16 * PITCH) + sbyte;
                ldm4(a + OF_AHI, ah[mt]);
                ldm4(a + OF_ALO, al[mt]);
            }
            uint32_t bh[4][4], bl[4][4];
            #pragma unroll
            for (int q = 0; q < 4; ++q) {
                uint32_t a = sb + bLB + (uint32_t)q * (16 * PITCH) + sbyte;
                ldm4(a + OF_BHI, bh[q]);
                ldm4(a + OF_BLO, bl[q]);
            }
            #pragma unroll
            for (int mt = 0; mt < 2; ++mt)
                #pragma unroll
                for (int q = 0; q < 4; ++q)
                    #pragma unroll
                    for (int h = 0; h < 2; ++h) {
                        float* cc = acc[mt][q * 2 + h];
                        mma16816(cc, ah[mt], &bh[q][2 * h]);
                        mma16816(cc, ah[mt], &bl[q][2 * h]);
                        mma16816(cc, al[mt], &bh[q][2 * h]);
                    }
        }
    }

    // ---- epilogue: store partials ----
    const int r4 = lane >> 2, c4 = lane & 3;
    #pragma unroll
    for (int mt = 0; mt < 2; ++mt) {
        const size_t rg = (size_t)row0 + w * 32 + mt * 16 + r4;
        float* base = &g_part[((size_t)ks * M_ALL + rg) * D_SZ];
        #pragma unroll
        for (int nt = 0; nt < 8; ++nt) {
            float2 v0 = make_float2(acc[mt][nt][0], acc[mt][nt][1]);
            float2 v1 = make_float2(acc[mt][nt][2], acc[mt][nt][3]);
            *(float2*)(base + nt * 8 + c4 * 2)                 = v0;
            *(float2*)(base + 8 * (size_t)D_SZ + nt * 8 + c4 * 2) = v1;
        }
    }
}

// ---- K2: reduce k-slices + bias -> g_sup --------------------------------------
__global__ void reduce_kernel(const float* __restrict__ bias) {
    int idx = blockIdx.x * 256 + threadIdx.x;          // covers M_ALL*D exactly
    float s = bias[idx & 63];
    #pragma unroll
    for (int ks = 0; ks < KSPLIT; ++ks)
        s += g_part[(size_t)ks * M_ALL * D_SZ + idx];
    g_sup[idx] = s;
}

// ---- K3: warp-per-episode sims/softmax/preds/argmax/CE ------------------------
__global__ void sim_kernel(const float* __restrict__ onehot,
                           const int* __restrict__ tgty)
{
    const int w    = (blockIdx.x * blockDim.x + threadIdx.x) >> 5;   // episode
    const int lane = threadIdx.x & 31;
    const unsigned FULL = 0xFFFFFFFFu;

    const float* tgt = &g_sup[(size_t)(M_SUP + w) * D_SZ];
    float sim = -3.0e38f;
    if (lane < S_SZ) {
        const float* sp = &g_sup[(size_t)(w * S_SZ + lane) * D_SZ];
        float dot = 0.f, mag = 0.f;
        #pragma unroll
        for (int d = 0; d < D_SZ; ++d) {
            float s = sp[d];
            dot += s * tgt[d];
            mag += s * s;
        }
        sim = dot * rsqrtf(fmaxf(mag, 1e-10f));
    }
    float m = sim;
    #pragma unroll
    for (int o = 16; o; o >>= 1) m = fmaxf(m, __shfl_xor_sync(FULL, m, o));
    float e = (lane < S_SZ) ? expf(sim - m) : 0.f;
    float sum = e;
    #pragma unroll
    for (int o = 16; o; o >>= 1) sum += __shfl_xor_sync(FULL, sum, o);
    float attn = e / sum;

    float p = 0.f;
    #pragma unroll
    for (int s = 0; s < S_SZ; ++s) {
        float a = __shfl_sync(FULL, attn, s);
        if (lane < C_SZ) p += a * onehot[((size_t)w * S_SZ + s) * C_SZ + lane];
    }

    float bv = (lane < C_SZ) ? p : -3.0e38f;
    int   bi = (lane < C_SZ) ? lane : 999;
    #pragma unroll
    for (int o = 16; o; o >>= 1) {
        float ov = __shfl_xor_sync(FULL, bv, o);
        int   oi = __shfl_xor_sync(FULL, bi, o);
        if (ov > bv || (ov == bv && oi < bi)) { bv = ov; bi = oi; }
    }
    float pm = (lane < C_SZ) ? p : -3.0e38f;
    #pragma unroll
    for (int o = 16; o; o >>= 1) pm = fmaxf(pm, __shfl_xor_sync(FULL, pm, o));
    float ee = (lane < C_SZ) ? expf(p - pm) : 0.f;
    float lse = ee;
    #pragma unroll
    for (int o = 16; o; o >>= 1) lse += __shfl_xor_sync(FULL, lse, o);

    int y = tgty[w];
    float py = __shfl_sync(FULL, p, y);
    if (lane == 0) {
        g_pb[w]        = (bi == y) ? 1.f : 0.f;
        g_pb[B_SZ + w] = -(py - pm - logf(lse));
    }
}

// ---- K4: deterministic final reduction -> d_out -------------------------------
__global__ void finalize_kernel(float* __restrict__ out) {
    __shared__ float sc[B_SZ], sl[B_SZ];
    int t = threadIdx.x;
    sc[t] = g_pb[t];
    sl[t] = g_pb[B_SZ + t];
    __syncthreads();
    for (int off = 128; off > 0; off >>= 1) {
        if (t < off) { sc[t] += sc[t + off]; sl[t] += sl[t + off]; }
        __syncthreads();
    }
    if (t == 0) {
        out[0] = sc[0] * (1.f / (float)B_SZ);
        out[1] = sl[0] * (1.f / (float)B_SZ);
    }
}

// ---------------------------------------------------------------------------
extern "C" void kernel_launch(void* const* d_in, const int* in_sizes, int n_in,
                              void* d_out, int out_size)
{
    const float* img    = (const float*)d_in[0];   // [256,20,20000]
    const float* onehot = (const float*)d_in[1];   // [256,20,20]
    const float* tgtim  = (const float*)d_in[2];   // [256,20000]
    const int*   tgty   = (const int*)  d_in[3];   // [256]
    const float* W      = (const float*)d_in[4];   // [64,20000]
    const float* bias   = (const float*)d_in[5];   // [64]
    float* out = (float*)d_out;                    // [2]

    cudaFuncSetAttribute(gemm_kernel,
                         cudaFuncAttributeMaxDynamicSharedMemorySize, SMEM_TOTAL);

    prep_w_kernel<<<(D_SZ * V_SZ) / 256, 256>>>(W);
    gemm_kernel<<<dim3(M_ALL / 128, KSPLIT), 128, SMEM_TOTAL>>>(img, tgtim);
    reduce_kernel<<<(M_ALL * D_SZ) / 256, 256>>>(bias);
    sim_kernel<<<B_SZ / 8, 256>>>(onehot, tgty);
    finalize_kernel<<<1, B_SZ>>>(out);
}